// round 16
// baseline (speedup 1.0000x reference)
#include <cuda_runtime.h>
#include <cuda_bf16.h>
#include <cuda_fp16.h>
#include <float.h>
#include <stdint.h>

#define L_DIM 2048
#define NB 2
#define E_DIM 1024
#define H_DIM 16
#define HD_DIM 64
#define R_DIM 8
#define T_DIM (L_DIM*NB)   // 4096 tokens
#define LORA_SCALE 4.0f
#define ATTN_SCALE 0.125f  // 64^-0.5
#define KT 64              // keys per fused tile
#define NTILES (L_DIM/KT)  // 32

// Scratch (static device globals — no allocations allowed)
static __device__ float g_ao[(size_t)T_DIM*E_DIM];
static __device__ __half g_w[(size_t)NB*H_DIM*L_DIM*L_DIM];  // unnormalized exp weights
static __device__ float g_mtile[(size_t)NB*H_DIM*NTILES*L_DIM];
static __device__ float g_mfin[(size_t)NB*H_DIM*L_DIM];
static __device__ float g_sfin[(size_t)NB*H_DIM*L_DIM];
static __device__ float g_xa[(size_t)4*T_DIM*R_DIM];
static __device__ unsigned char g_mask[NB*L_DIM];
// pre-split projection inputs/outputs
static __device__ __nv_bfloat16 g_xh[(size_t)T_DIM*E_DIM], g_xl[(size_t)T_DIM*E_DIM];
static __device__ __nv_bfloat16 g_wsh[4][(size_t)E_DIM*E_DIM];  // W hi: q,k,v,o
static __device__ __nv_bfloat16 g_wsl[4][(size_t)E_DIM*E_DIM];  // W lo
static __device__ __nv_bfloat16 g_qh[(size_t)T_DIM*E_DIM], g_ql[(size_t)T_DIM*E_DIM];
static __device__ __nv_bfloat16 g_kh[(size_t)T_DIM*E_DIM], g_kl[(size_t)T_DIM*E_DIM];
static __device__ __half g_vf[(size_t)T_DIM*E_DIM];

// ===================== mma.sync / ldmatrix / cp.async helpers ===============
__device__ __forceinline__ void mma_bf16(float* c,
    uint32_t a0, uint32_t a1, uint32_t a2, uint32_t a3,
    uint32_t b0, uint32_t b1)
{
    asm volatile(
        "mma.sync.aligned.m16n8k16.row.col.f32.bf16.bf16.f32 "
        "{%0,%1,%2,%3},{%4,%5,%6,%7},{%8,%9},{%0,%1,%2,%3};"
        : "+f"(c[0]), "+f"(c[1]), "+f"(c[2]), "+f"(c[3])
        : "r"(a0), "r"(a1), "r"(a2), "r"(a3), "r"(b0), "r"(b1));
}
__device__ __forceinline__ void mma_f16(float* c,
    uint32_t a0, uint32_t a1, uint32_t a2, uint32_t a3,
    uint32_t b0, uint32_t b1)
{
    asm volatile(
        "mma.sync.aligned.m16n8k16.row.col.f32.f16.f16.f32 "
        "{%0,%1,%2,%3},{%4,%5,%6,%7},{%8,%9},{%0,%1,%2,%3};"
        : "+f"(c[0]), "+f"(c[1]), "+f"(c[2]), "+f"(c[3])
        : "r"(a0), "r"(a1), "r"(a2), "r"(a3), "r"(b0), "r"(b1));
}
__device__ __forceinline__ void ldm_x4(uint32_t& r0, uint32_t& r1,
                                       uint32_t& r2, uint32_t& r3, uint32_t a)
{
    asm volatile("ldmatrix.sync.aligned.m8n8.x4.shared.b16 {%0,%1,%2,%3}, [%4];"
                 : "=r"(r0), "=r"(r1), "=r"(r2), "=r"(r3) : "r"(a));
}
__device__ __forceinline__ void ldm_x4_trans(uint32_t& r0, uint32_t& r1,
                                             uint32_t& r2, uint32_t& r3, uint32_t a)
{
    asm volatile("ldmatrix.sync.aligned.m8n8.x4.trans.shared.b16 {%0,%1,%2,%3}, [%4];"
                 : "=r"(r0), "=r"(r1), "=r"(r2), "=r"(r3) : "r"(a));
}
#define CP_ASYNC16(dst_u32, src_ptr) \
    asm volatile("cp.async.cg.shared.global [%0], [%1], 16;" \
                 :: "r"(dst_u32), "l"(src_ptr) : "memory")
#define CP_COMMIT() asm volatile("cp.async.commit_group;" ::: "memory")
#define CP_WAIT0()  asm volatile("cp.async.wait_group 0;" ::: "memory")

__device__ __forceinline__ void split2(float x, float y, uint32_t& h, uint32_t& l)
{
    __nv_bfloat162 hh = __floats2bfloat162_rn(x, y);
    float rx = x - __bfloat162float(__low2bfloat16(hh));
    float ry = y - __bfloat162float(__high2bfloat16(hh));
    __nv_bfloat162 ll = __floats2bfloat162_rn(rx, ry);
    h = *(uint32_t*)&hh;
    l = *(uint32_t*)&ll;
}

// ---------------------------------------------------------------------------
// fp32 -> bf16 hi/lo splits: X variant (pointer dst) and merged 4-W variant
// ---------------------------------------------------------------------------
__global__ __launch_bounds__(256) void split_x_kernel(
    const float* __restrict__ src, int n4)
{
    int i = blockIdx.x * 256 + threadIdx.x;
    if (i >= n4) return;
    size_t o = (size_t)i * 4;
    float4 v = *(const float4*)&src[o];
    uint32_t h0, l0, h1, l1;
    split2(v.x, v.y, h0, l0);
    split2(v.z, v.w, h1, l1);
    *(uint2*)&g_xh[o] = make_uint2(h0, h1);
    *(uint2*)&g_xl[o] = make_uint2(l0, l1);
}

__global__ __launch_bounds__(256) void split_w_kernel(
    const float* __restrict__ W0, const float* __restrict__ W1,
    const float* __restrict__ W2, const float* __restrict__ W3)
{
    int w = blockIdx.y;
    const float* src = (w == 0) ? W0 : (w == 1) ? W1 : (w == 2) ? W2 : W3;
    const int n4 = (E_DIM * E_DIM) / 4;
    int i = blockIdx.x * 256 + threadIdx.x;
    if (i >= n4) return;
    size_t o = (size_t)i * 4;
    float4 v = *(const float4*)&src[o];
    uint32_t h0, l0, h1, l1;
    split2(v.x, v.y, h0, l0);
    split2(v.z, v.w, h1, l1);
    *(uint2*)&g_wsh[w][o] = make_uint2(h0, h1);
    *(uint2*)&g_wsl[w][o] = make_uint2(l0, l1);
}

// ---------------------------------------------------------------------------
// Mask normalization
// ---------------------------------------------------------------------------
__global__ __launch_bounds__(1024) void mask_prep_kernel(const void* __restrict__ mraw)
{
    __shared__ int s_notint, s_notfloat;
    if (threadIdx.x == 0) { s_notint = 0; s_notfloat = 0; }
    __syncthreads();

    const unsigned int* u = (const unsigned int*)mraw;
    const unsigned char* b = (const unsigned char*)mraw;
    const int NM = NB * L_DIM;

    int notint = 0, notfloat = 0;
    for (int i = threadIdx.x; i < NM / 4; i += 1024) {
        unsigned int v = u[i];
        if (v > 1u) notint = 1;
        if (v != 0u && v != 0x3F800000u) notfloat = 1;
    }
    if (notint)   atomicOr(&s_notint, 1);
    if (notfloat) atomicOr(&s_notfloat, 1);
    __syncthreads();

    bool isWord = (s_notint == 0) || (s_notfloat == 0);
    for (int i = threadIdx.x; i < NM; i += 1024) {
        unsigned char m = isWord ? (unsigned char)(u[i] != 0u)
                                 : (unsigned char)(b[i] != 0);
        g_mask[i] = m;
    }
}

// ---------------------------------------------------------------------------
// LoRA first stage: xa[t][r] = sum_i X[t][i] * A[r][i]
// ---------------------------------------------------------------------------
__global__ __launch_bounds__(256) void lora_xa_kernel(
    const float* __restrict__ Xext,
    const float* __restrict__ A0, const float* __restrict__ A1,
    const float* __restrict__ A2, int mode)
{
    const float* X = mode ? g_ao : Xext;
    int t = blockIdx.x;
    int p = blockIdx.y;
    const float* A = (p == 0) ? A0 : (p == 1) ? A1 : A2;
    float* out = g_xa + ((size_t)(mode ? 3 : p)) * T_DIM * R_DIM;

    int warp = threadIdx.x >> 5, lane = threadIdx.x & 31;
    const float* x = X + (size_t)t * E_DIM;
    const float* a = A + (size_t)warp * E_DIM;
    float s = 0.f;
    for (int i = lane * 4; i < E_DIM; i += 128) {
        float4 xv = *(const float4*)(x + i);
        float4 av = *(const float4*)(a + i);
        s += xv.x*av.x + xv.y*av.y + xv.z*av.z + xv.w*av.w;
    }
    #pragma unroll
    for (int off = 16; off; off >>= 1) s += __shfl_xor_sync(0xffffffffu, s, off);
    if (lane == 0) out[(size_t)t * R_DIM + warp] = s;
}

// ---------------------------------------------------------------------------
// Projection GEMM v2: cp.async double-buffered + ldmatrix, pre-split inputs.
// ---------------------------------------------------------------------------
#define P_LDA 40
#define PARR (128*P_LDA*2)        // 10240 B per array
#define PBUF (4*PARR)             // 40960 B per buffer {Ah, Al, Bh, Bl}
#define POFF_LORA (2*PBUF)        // 81920
#define POFF_BIAS (POFF_LORA + 4096)
#define PROJ_SMEM (POFF_BIAS + 512)   // 86528

__global__ __launch_bounds__(256, 2) void proj_mma_kernel(
    const float* __restrict__ b0, const float* __restrict__ Bl0,
    const float* __restrict__ b1, const float* __restrict__ Bl1,
    const float* __restrict__ b2, const float* __restrict__ Bl2,
    float* __restrict__ Oext, int mode, float oscale0)
{
    extern __shared__ char psm[];
    const uint32_t sbase = (uint32_t)__cvta_generic_to_shared(psm);
    float* lora_sm = (float*)(psm + POFF_LORA);
    float* bias_sm = (float*)(psm + POFF_BIAS);

    int z = blockIdx.z;
    const __nv_bfloat16* Xh = g_xh;
    const __nv_bfloat16* Xl = g_xl;
    const __nv_bfloat16* Wh = g_wsh[mode ? 3 : z];
    const __nv_bfloat16* Wl = g_wsl[mode ? 3 : z];
    const float* bias = (z == 0) ? b0  : (z == 1) ? b1  : b2;
    const float* Bl   = (z == 0) ? Bl0 : (z == 1) ? Bl1 : Bl2;
    const float* xa   = g_xa + ((size_t)(mode ? 3 : z)) * T_DIM * R_DIM;
    float oscale      = (mode == 0 && z == 0) ? oscale0 : 1.0f;

    int kind;                        // 0 = bf16 hi/lo, 1 = fp16, 2 = fp32
    __nv_bfloat16 *Oh = nullptr, *Ol = nullptr;
    __half* Of = nullptr;
    float* O32 = nullptr;
    if (mode) { kind = 2; O32 = Oext; }
    else if (z == 0) { kind = 0; Oh = g_qh; Ol = g_ql; }
    else if (z == 1) { kind = 0; Oh = g_kh; Ol = g_kl; }
    else { kind = 1; Of = g_vf; }

    const int m0 = blockIdx.y * 128;
    const int n0 = blockIdx.x * 128;

    int tid = threadIdx.x;
    int wid = tid >> 5, lane = tid & 31;
    int warp_m = wid & 1;
    int warp_n = wid >> 1;

    for (int i = tid; i < 128 * 8; i += 256)
        lora_sm[i] = Bl[(size_t)(n0 + (i >> 3)) * R_DIM + (i & 7)];
    for (int i = tid; i < 128; i += 256)
        bias_sm[i] = bias[n0 + i];

    // stage chunk 0 into buffer 0
    #pragma unroll
    for (int i = 0; i < 2; i++) {
        int idx = tid + i * 256;        // 0..511
        int row = idx >> 2;             // 0..127
        int hq = (idx & 3) * 8;         // 0..24
        size_t gx = (size_t)(m0 + row) * E_DIM + hq;
        size_t gw = (size_t)(n0 + row) * E_DIM + hq;
        uint32_t d = sbase + (row * P_LDA + hq) * 2;
        CP_ASYNC16(d,            &Xh[gx]);
        CP_ASYNC16(d + PARR,     &Xl[gx]);
        CP_ASYNC16(d + 2 * PARR, &Wh[gw]);
        CP_ASYNC16(d + 3 * PARR, &Wl[gw]);
    }
    CP_COMMIT();

    // ldmatrix per-lane pattern
    const int frow = ((lane >> 3) & 1) * 8 + (lane & 7);
    const int fcol = (lane >> 4) * 8;

    float acc[4][4][4];
    #pragma unroll
    for (int mt = 0; mt < 4; mt++)
        #pragma unroll
        for (int nt = 0; nt < 4; nt++)
            #pragma unroll
            for (int r = 0; r < 4; r++) acc[mt][nt][r] = 0.f;

    int buf = 0;
    for (int kc = 0; kc < E_DIM / 32; kc++) {
        CP_WAIT0();
        __syncthreads();

        if (kc + 1 < E_DIM / 32) {
            int k0 = (kc + 1) * 32;
            uint32_t dst = sbase + (buf ^ 1) * PBUF;
            #pragma unroll
            for (int i = 0; i < 2; i++) {
                int idx = tid + i * 256;
                int row = idx >> 2;
                int hq = (idx & 3) * 8;
                size_t gx = (size_t)(m0 + row) * E_DIM + k0 + hq;
                size_t gw = (size_t)(n0 + row) * E_DIM + k0 + hq;
                uint32_t d = dst + (row * P_LDA + hq) * 2;
                CP_ASYNC16(d,            &Xh[gx]);
                CP_ASYNC16(d + PARR,     &Xl[gx]);
                CP_ASYNC16(d + 2 * PARR, &Wh[gw]);
                CP_ASYNC16(d + 3 * PARR, &Wl[gw]);
            }
            CP_COMMIT();
        }

        const uint32_t uA = sbase + buf * PBUF
                          + ((warp_m * 64 + frow) * P_LDA + fcol) * 2;
        const uint32_t uB = sbase + buf * PBUF + 2 * PARR
                          + ((warp_n * 32 + frow) * P_LDA + fcol) * 2;

        #pragma unroll
        for (int ks = 0; ks < 2; ks++) {
            uint32_t ah[4][4], al[4][4];
            #pragma unroll
            for (int mt = 0; mt < 4; mt++) {
                uint32_t a0 = uA + (mt * 16 * P_LDA) * 2 + ks * 32;
                ldm_x4(ah[mt][0], ah[mt][1], ah[mt][2], ah[mt][3], a0);
                ldm_x4(al[mt][0], al[mt][1], al[mt][2], al[mt][3], a0 + PARR);
            }
            #pragma unroll
            for (int ntp = 0; ntp < 2; ntp++) {
                uint32_t bhA0, bhB0, bhA1, bhB1, blA0, blB0, blA1, blB1;
                uint32_t bb = uB + (ntp * 16 * P_LDA) * 2 + ks * 32;
                ldm_x4(bhA0, bhB0, bhA1, bhB1, bb);
                ldm_x4(blA0, blB0, blA1, blB1, bb + PARR);
                #pragma unroll
                for (int mt = 0; mt < 4; mt++) {
                    mma_bf16(acc[mt][2*ntp],   ah[mt][0], ah[mt][1], ah[mt][2], ah[mt][3], bhA0, bhA1);
                    mma_bf16(acc[mt][2*ntp],   ah[mt][0], ah[mt][1], ah[mt][2], ah[mt][3], blA0, blA1);
                    mma_bf16(acc[mt][2*ntp],   al[mt][0], al[mt][1], al[mt][2], al[mt][3], bhA0, bhA1);
                    mma_bf16(acc[mt][2*ntp+1], ah[mt][0], ah[mt][1], ah[mt][2], ah[mt][3], bhB0, bhB1);
                    mma_bf16(acc[mt][2*ntp+1], ah[mt][0], ah[mt][1], ah[mt][2], ah[mt][3], blB0, blB1);
                    mma_bf16(acc[mt][2*ntp+1], al[mt][0], al[mt][1], al[mt][2], al[mt][3], bhB0, bhB1);
                }
            }
        }
        buf ^= 1;
    }

    #pragma unroll
    for (int mt = 0; mt < 4; mt++) {
        int r0 = m0 + warp_m * 64 + mt * 16 + (lane >> 2);
        int r1 = r0 + 8;
        float xr0[8], xr1[8];
        *(float4*)(xr0)     = *(const float4*)&xa[(size_t)r0 * R_DIM];
        *(float4*)(xr0 + 4) = *(const float4*)&xa[(size_t)r0 * R_DIM + 4];
        *(float4*)(xr1)     = *(const float4*)&xa[(size_t)r1 * R_DIM];
        *(float4*)(xr1 + 4) = *(const float4*)&xa[(size_t)r1 * R_DIM + 4];
        #pragma unroll
        for (int nt = 0; nt < 4; nt++) {
            int col = warp_n * 32 + nt * 8 + (lane & 3) * 2;
            const float* bl0 = &lora_sm[col * 8];
            const float* bl1 = &lora_sm[(col + 1) * 8];
            float lr00 = 0.f, lr01 = 0.f, lr10 = 0.f, lr11 = 0.f;
            #pragma unroll
            for (int r = 0; r < 8; r++) {
                lr00 += xr0[r] * bl0[r];
                lr01 += xr0[r] * bl1[r];
                lr10 += xr1[r] * bl0[r];
                lr11 += xr1[r] * bl1[r];
            }
            float2 v0, v1;
            v0.x = (acc[mt][nt][0] + bias_sm[col]     + LORA_SCALE * lr00) * oscale;
            v0.y = (acc[mt][nt][1] + bias_sm[col + 1] + LORA_SCALE * lr01) * oscale;
            v1.x = (acc[mt][nt][2] + bias_sm[col]     + LORA_SCALE * lr10) * oscale;
            v1.y = (acc[mt][nt][3] + bias_sm[col + 1] + LORA_SCALE * lr11) * oscale;
            size_t o0 = (size_t)r0 * E_DIM + n0 + col;
            size_t o1 = (size_t)r1 * E_DIM + n0 + col;
            if (kind == 0) {
                uint32_t hh, ll;
                split2(v0.x, v0.y, hh, ll);
                *(uint32_t*)&Oh[o0] = hh; *(uint32_t*)&Ol[o0] = ll;
                split2(v1.x, v1.y, hh, ll);
                *(uint32_t*)&Oh[o1] = hh; *(uint32_t*)&Ol[o1] = ll;
            } else if (kind == 1) {
                *(__half2*)&Of[o0] = __floats2half2_rn(v0.x, v0.y);
                *(__half2*)&Of[o1] = __floats2half2_rn(v1.x, v1.y);
            } else {
                *(float2*)&O32[o0] = v0;
                *(float2*)&O32[o1] = v1;
            }
        }
    }
}

// ---------------------------------------------------------------------------
// Fused attention v3 (unchanged from r15): cp.async double-buffered K/V +
// ldmatrix + smem-staged coalesced w' stores.
// ---------------------------------------------------------------------------
#define QLD 72
#define QARR (128*QLD*2)          // 18432 B
#define KARR (64*QLD*2)           // 9216 B
#define OFF_QH 0
#define OFF_QL QARR
#define OFF_KV (2*QARR)           // per buf {KH, KL, V} = 3*KARR
#define KVSTRIDE (3*KARR)         // 27648
#define OFF_MS (OFF_KV + 2*KVSTRIDE)   // 92160
#define WLD 72
#define OFF_WST (OFF_MS + 2048)        // 94208
#define ATT_SMEM (OFF_WST + 128*WLD*2) // 112640

__global__ __launch_bounds__(256, 2) void attn_fused_kernel()
{
    extern __shared__ char smem[];
    unsigned char* msk_s = (unsigned char*)(smem + OFF_MS);
    __half* wst = (__half*)(smem + OFF_WST);
    const uint32_t sbase = (uint32_t)__cvta_generic_to_shared(smem);

    int z = blockIdx.y;
    int n = z >> 4, h = z & 15;
    const size_t hb = (size_t)n * E_DIM + h * HD_DIM;
    const size_t zb = (size_t)z * L_DIM * L_DIM;
    const int lda = NB * E_DIM;
    const int m0 = blockIdx.x * 128;

    int tid = threadIdx.x;
    int wid = tid >> 5, lane = tid & 31;
    const int rg0 = m0 + wid * 16 + (lane >> 2);

    #pragma unroll
    for (int i = 0; i < 4; i++) {
        int idx = tid + i * 256;
        int row = idx >> 3;
        int hq = (idx & 7) * 8;
        size_t go = hb + (size_t)(m0 + row) * lda + hq;
        uint32_t d = sbase + OFF_QH + (row * QLD + hq) * 2;
        CP_ASYNC16(d, &g_qh[go]);
        CP_ASYNC16(d + QARR, &g_ql[go]);
    }
    for (int i = tid; i < L_DIM; i += 256)
        msk_s[i] = g_mask[n * L_DIM + i];

    #pragma unroll
    for (int i = 0; i < 2; i++) {
        int idx = tid + i * 256;
        int row = idx >> 3;
        int hq = (idx & 7) * 8;
        size_t go = hb + (size_t)(row) * lda + hq;
        uint32_t d = sbase + OFF_KV + (row * QLD + hq) * 2;
        CP_ASYNC16(d, &g_kh[go]);
        CP_ASYNC16(d + KARR, &g_kl[go]);
        CP_ASYNC16(d + 2 * KARR, &g_vf[go]);
    }
    CP_COMMIT();

    const int frow = ((lane >> 3) & 1) * 8 + (lane & 7);
    const int fcol = (lane >> 4) * 8;
    const uint32_t uQh = sbase + OFF_QH + ((wid * 16 + frow) * QLD + fcol) * 2;
    const uint32_t uQl = uQh + QARR;
    const int vrow = ((lane >> 4) << 3) + (lane & 7);
    const int vcol = ((lane >> 3) & 1) << 3;

    const int srow = wid * 16 + (lane >> 2);
    const int scol = (lane & 3) * 2;

    float m0r = -FLT_MAX, m1r = -FLT_MAX, s0 = 0.f, s1 = 0.f;
    float acc[8][4];
    #pragma unroll
    for (int dt = 0; dt < 8; dt++)
        #pragma unroll
        for (int r = 0; r < 4; r++) acc[dt][r] = 0.f;

    int buf = 0;
    for (int kt = 0; kt < NTILES; kt++) {
        CP_WAIT0();
        __syncthreads();

        if (kt + 1 < NTILES) {
            int kb = (kt + 1) * KT;
            uint32_t dst = sbase + OFF_KV + (buf ^ 1) * KVSTRIDE;
            #pragma unroll
            for (int i = 0; i < 2; i++) {
                int idx = tid + i * 256;
                int row = idx >> 3;
                int hq = (idx & 7) * 8;
                size_t go = hb + (size_t)(kb + row) * lda + hq;
                uint32_t d = dst + (row * QLD + hq) * 2;
                CP_ASYNC16(d, &g_kh[go]);
                CP_ASYNC16(d + KARR, &g_kl[go]);
                CP_ASYNC16(d + 2 * KARR, &g_vf[go]);
            }
            CP_COMMIT();
        }

        const uint32_t uKh = sbase + OFF_KV + buf * KVSTRIDE + (frow * QLD + fcol) * 2;
        const uint32_t uKl = uKh + KARR;
        const uint32_t uV  = sbase + OFF_KV + buf * KVSTRIDE + 2 * KARR
                           + (vrow * QLD + vcol) * 2;
        int kbase = kt * KT;

        float f[8][4];
        #pragma unroll
        for (int nt = 0; nt < 8; nt++)
            #pragma unroll
            for (int r = 0; r < 4; r++) f[nt][r] = 0.f;

        #pragma unroll
        for (int ks = 0; ks < 4; ks++) {
            uint32_t qh0, qh1, qh2, qh3, ql0, ql1, ql2, ql3;
            ldm_x4(qh0, qh1, qh2, qh3, uQh + ks * 32);
            ldm_x4(ql0, ql1, ql2, ql3, uQl + ks * 32);
            #pragma unroll
            for (int ntp = 0; ntp < 4; ntp++) {
                uint32_t bhA0, bhB0, bhA1, bhB1, blA0, blB0, blA1, blB1;
                ldm_x4(bhA0, bhB0, bhA1, bhB1, uKh + (ntp * 16 * QLD) * 2 + ks * 32);
                ldm_x4(blA0, blB0, blA1, blB1, uKl + (ntp * 16 * QLD) * 2 + ks * 32);
                mma_bf16(f[2*ntp],   qh0, qh1, qh2, qh3, bhA0, bhA1);
                mma_bf16(f[2*ntp],   qh0, qh1, qh2, qh3, blA0, blA1);
                mma_bf16(f[2*ntp],   ql0, ql1, ql2, ql3, bhA0, bhA1);
                mma_bf16(f[2*ntp+1], qh0, qh1, qh2, qh3, bhB0, bhB1);
                mma_bf16(f[2*ntp+1], qh0, qh1, qh2, qh3, blB0, blB1);
                mma_bf16(f[2*ntp+1], ql0, ql1, ql2, ql3, bhB0, bhB1);
            }
        }

        int cb = kbase + (lane & 3) * 2;
        float tm0 = -FLT_MAX, tm1 = -FLT_MAX;
        unsigned mka = 0, mkb = 0;
        #pragma unroll
        for (int nt = 0; nt < 8; nt++) {
            bool ma = msk_s[cb + nt * 8] != 0;
            bool mb = msk_s[cb + nt * 8 + 1] != 0;
            if (ma) mka |= (1u << nt);
            if (mb) mkb |= (1u << nt);
            tm0 = fmaxf(tm0, ma ? -FLT_MAX : f[nt][0]);
            tm0 = fmaxf(tm0, mb ? -FLT_MAX : f[nt][1]);
            tm1 = fmaxf(tm1, ma ? -FLT_MAX : f[nt][2]);
            tm1 = fmaxf(tm1, mb ? -FLT_MAX : f[nt][3]);
        }
        tm0 = fmaxf(tm0, __shfl_xor_sync(0xffffffffu, tm0, 1));
        tm0 = fmaxf(tm0, __shfl_xor_sync(0xffffffffu, tm0, 2));
        tm1 = fmaxf(tm1, __shfl_xor_sync(0xffffffffu, tm1, 1));
        tm1 = fmaxf(tm1, __shfl_xor_sync(0xffffffffu, tm1, 2));

        float mn0 = fmaxf(m0r, tm0);
        float mn1 = fmaxf(m1r, tm1);
        float sc0 = __expf(m0r - mn0);
        float sc1 = __expf(m1r - mn1);
        s0 *= sc0; s1 *= sc1;
        #pragma unroll
        for (int dt = 0; dt < 8; dt++) {
            acc[dt][0] *= sc0; acc[dt][1] *= sc0;
            acc[dt][2] *= sc1; acc[dt][3] *= sc1;
        }
        m0r = mn0; m1r = mn1;

        uint32_t wA[8], wB[8];
        #pragma unroll
        for (int nt = 0; nt < 8; nt++) {
            bool ma = (mka >> nt) & 1, mb = (mkb >> nt) & 1;
            float e0 = ma ? 0.f : __expf(f[nt][0] - mn0);
            float e1 = mb ? 0.f : __expf(f[nt][1] - mn0);
            float e2 = ma ? 0.f : __expf(f[nt][2] - mn1);
            float e3 = mb ? 0.f : __expf(f[nt][3] - mn1);
            s0 += e0 + e1;
            s1 += e2 + e3;
            __half2 w01 = __floats2half2_rn(e0, e1);
            __half2 w23 = __floats2half2_rn(e2, e3);
            wA[nt] = *(uint32_t*)&w01;
            wB[nt] = *(uint32_t*)&w23;
            int col = scol + nt * 8;
            *(uint32_t*)&wst[srow * WLD + col] = wA[nt];
            *(uint32_t*)&wst[(srow + 8) * WLD + col] = wB[nt];
        }
        if ((lane & 3) == 0) {
            g_mtile[((size_t)z * NTILES + kt) * L_DIM + rg0] = mn0;
            g_mtile[((size_t)z * NTILES + kt) * L_DIM + rg0 + 8] = mn1;
        }

        #pragma unroll
        for (int kk = 0; kk < 4; kk++) {
            uint32_t vbase = uV + (kk * 16 * QLD) * 2;
            #pragma unroll
            for (int dtp = 0; dtp < 4; dtp++) {
                uint32_t vA0, vB0, vA1, vB1;
                ldm_x4_trans(vA0, vB0, vA1, vB1, vbase + (dtp * 16) * 2);
                mma_f16(acc[2*dtp],   wA[2*kk], wB[2*kk], wA[2*kk+1], wB[2*kk+1], vA0, vA1);
                mma_f16(acc[2*dtp+1], wA[2*kk], wB[2*kk], wA[2*kk+1], wB[2*kk+1], vB0, vB1);
            }
        }

        __syncthreads();
        #pragma unroll
        for (int i = 0; i < 4; i++) {
            int idx = tid + i * 256;
            int row = idx >> 3;
            int cq = (idx & 7) * 8;
            uint4 v = *(const uint4*)&wst[row * WLD + cq];
            *(uint4*)&g_w[zb + (size_t)(m0 + row) * L_DIM + kbase + cq] = v;
        }
        buf ^= 1;
    }

    s0 += __shfl_xor_sync(0xffffffffu, s0, 1);
    s0 += __shfl_xor_sync(0xffffffffu, s0, 2);
    s1 += __shfl_xor_sync(0xffffffffu, s1, 1);
    s1 += __shfl_xor_sync(0xffffffffu, s1, 2);

    float inv0 = (s0 > 0.f) ? 1.f / s0 : 0.f;
    float inv1 = (s1 > 0.f) ? 1.f / s1 : 0.f;
    if ((lane & 3) == 0) {
        g_mfin[(size_t)z * L_DIM + rg0] = m0r;
        g_mfin[(size_t)z * L_DIM + rg0 + 8] = m1r;
        g_sfin[(size_t)z * L_DIM + rg0] = s0;
        g_sfin[(size_t)z * L_DIM + rg0 + 8] = s1;
    }
    #pragma unroll
    for (int dt = 0; dt < 8; dt++) {
        int d = dt * 8 + (lane & 3) * 2;
        *(float2*)&g_ao[((size_t)rg0 * NB + n) * E_DIM + h * HD_DIM + d] =
            make_float2(acc[dt][0] * inv0, acc[dt][1] * inv0);
        *(float2*)&g_ao[((size_t)(rg0 + 8) * NB + n) * E_DIM + h * HD_DIM + d] =
            make_float2(acc[dt][2] * inv1, acc[dt][3] * inv1);
    }
}

// ---------------------------------------------------------------------------
// Head-mean of normalized weights
// ---------------------------------------------------------------------------
__global__ __launch_bounds__(256) void mean_kernel(float* __restrict__ out2)
{
    int l = blockIdx.x, n = blockIdx.y;
    __shared__ float fac[NTILES];
    int tid = threadIdx.x;
    int c0 = tid * 8;

    float wacc[8];
    #pragma unroll
    for (int j = 0; j < 8; j++) wacc[j] = 0.f;

    for (int h = 0; h < H_DIM; h++) {
        int z = n * H_DIM + h;
        if (tid < NTILES) {
            float mf = g_mfin[(size_t)z * L_DIM + l];
            float s  = g_sfin[(size_t)z * L_DIM + l];
            float inv = (s > 0.f) ? 1.f / s : 0.f;
            float mt = g_mtile[((size_t)z * NTILES + tid) * L_DIM + l];
            fac[tid] = __expf(mt - mf) * inv;
        }
        __syncthreads();
        float fc = fac[c0 >> 6];
        uint4 raw = *(const uint4*)&g_w[(size_t)z * L_DIM * L_DIM + (size_t)l * L_DIM + c0];
        const __half2* hp = (const __half2*)&raw;
        #pragma unroll
        for (int q = 0; q < 4; q++) {
            float2 v = __half22float2(hp[q]);
            wacc[q * 2]     += v.x * fc;
            wacc[q * 2 + 1] += v.y * fc;
        }
        __syncthreads();
    }

    const float invH = 1.0f / H_DIM;
    float4 o0 = make_float4(wacc[0]*invH, wacc[1]*invH, wacc[2]*invH, wacc[3]*invH);
    float4 o1 = make_float4(wacc[4]*invH, wacc[5]*invH, wacc[6]*invH, wacc[7]*invH);
    *(float4*)&out2[((size_t)l * NB + n) * L_DIM + c0]     = o0;
    *(float4*)&out2[((size_t)l * NB + n) * L_DIM + c0 + 4] = o1;
}

// ---------------------------------------------------------------------------
extern "C" void kernel_launch(void* const* d_in, const int* in_sizes, int n_in,
                              void* d_out, int out_size)
{
    (void)in_sizes; (void)n_in; (void)out_size;
    const float* query = (const float*)d_in[0];
    const void* mask_raw = d_in[1];
    const float* Wq = (const float*)d_in[2];
    const float* bq = (const float*)d_in[3];
    const float* Aq = (const float*)d_in[4];
    const float* Bq = (const float*)d_in[5];
    const float* Wk = (const float*)d_in[6];
    const float* bk = (const float*)d_in[7];
    const float* Ak = (const float*)d_in[8];
    const float* Bk = (const float*)d_in[9];
    const float* Wv = (const float*)d_in[10];
    const float* bv = (const float*)d_in[11];
    const float* Av = (const float*)d_in[12];
    const float* Bv = (const float*)d_in[13];
    const float* Wo = (const float*)d_in[14];
    const float* bo = (const float*)d_in[15];
    const float* Ao = (const float*)d_in[16];
    const float* Bo = (const float*)d_in[17];

    float* out  = (float*)d_out;
    float* out2 = out + (size_t)T_DIM * E_DIM;

    float* ao;
    cudaGetSymbolAddress((void**)&ao, g_ao);

    cudaFuncSetAttribute(attn_fused_kernel,
                         cudaFuncAttributeMaxDynamicSharedMemorySize, ATT_SMEM);
    cudaFuncSetAttribute(proj_mma_kernel,
                         cudaFuncAttributeMaxDynamicSharedMemorySize, PROJ_SMEM);

    const int NW4 = (E_DIM * E_DIM) / 4;
    const int NX4 = (T_DIM * E_DIM) / 4;

    // 0. Normalize mask; pre-split X and all W (merged launches)
    mask_prep_kernel<<<1, 1024>>>(mask_raw);
    split_x_kernel<<<NX4 / 256, 256>>>(query, NX4);
    split_w_kernel<<<dim3(NW4 / 256, 4), 256>>>(Wq, Wk, Wv, Wo);
    // 1. LoRA x@A^T for q,k,v
    lora_xa_kernel<<<dim3(T_DIM, 3), 256>>>(query, Aq, Ak, Av, 0);
    // 2. Q/K/V projections (cp.async + ldmatrix)
    proj_mma_kernel<<<dim3(8, 32, 3), 256, PROJ_SMEM>>>(bq, Bq, bk, Bk, bv, Bv,
                                                        nullptr, 0, ATTN_SCALE);
    // 3. Fused QK + online softmax + AV
    attn_fused_kernel<<<dim3(16, 32), 256, ATT_SMEM>>>();
    // 4. Head-mean weights output
    mean_kernel<<<dim3(L_DIM, NB), 256>>>(out2);
    // 5. LoRA x@A^T for output projection + split ao
    lora_xa_kernel<<<dim3(T_DIM, 1), 256>>>(nullptr, Ao, Ao, Ao, 1);
    split_x_kernel<<<NX4 / 256, 256>>>(ao, NX4);
    // 6. Output projection -> d_out
    proj_mma_kernel<<<dim3(8, 32, 1), 256, PROJ_SMEM>>>(bo, Bo, bo, Bo, bo, Bo,
                                                        out, 1, 1.0f);
}

// round 17
// speedup vs baseline: 1.1944x; 1.1944x over previous
#include <cuda_runtime.h>
#include <cuda_bf16.h>
#include <cuda_fp16.h>
#include <float.h>
#include <stdint.h>

#define L_DIM 2048
#define NB 2
#define E_DIM 1024
#define H_DIM 16
#define HD_DIM 64
#define R_DIM 8
#define T_DIM (L_DIM*NB)   // 4096 tokens
#define LORA_SCALE 4.0f
#define ATTN_SCALE 0.125f  // 64^-0.5
#define KT 64              // keys per fused tile
#define NTILES (L_DIM/KT)  // 32

// Scratch (static device globals — no allocations allowed)
static __device__ float g_ao[(size_t)T_DIM*E_DIM];
static __device__ __half g_w[(size_t)NB*H_DIM*L_DIM*L_DIM];  // unnormalized exp weights
static __device__ float g_mtile[(size_t)NB*H_DIM*NTILES*L_DIM];
static __device__ float g_mfin[(size_t)NB*H_DIM*L_DIM];
static __device__ float g_sfin[(size_t)NB*H_DIM*L_DIM];
static __device__ float g_xa[(size_t)4*T_DIM*R_DIM];
static __device__ unsigned char g_mask[NB*L_DIM];
// pre-split projection outputs
static __device__ __nv_bfloat16 g_qh[(size_t)T_DIM*E_DIM], g_ql[(size_t)T_DIM*E_DIM];
static __device__ __nv_bfloat16 g_kh[(size_t)T_DIM*E_DIM], g_kl[(size_t)T_DIM*E_DIM];
static __device__ __half g_vf[(size_t)T_DIM*E_DIM];

// ===================== mma.sync / ldmatrix / cp.async helpers ===============
__device__ __forceinline__ void mma_bf16(float* c,
    uint32_t a0, uint32_t a1, uint32_t a2, uint32_t a3,
    uint32_t b0, uint32_t b1)
{
    asm volatile(
        "mma.sync.aligned.m16n8k16.row.col.f32.bf16.bf16.f32 "
        "{%0,%1,%2,%3},{%4,%5,%6,%7},{%8,%9},{%0,%1,%2,%3};"
        : "+f"(c[0]), "+f"(c[1]), "+f"(c[2]), "+f"(c[3])
        : "r"(a0), "r"(a1), "r"(a2), "r"(a3), "r"(b0), "r"(b1));
}
__device__ __forceinline__ void mma_f16(float* c,
    uint32_t a0, uint32_t a1, uint32_t a2, uint32_t a3,
    uint32_t b0, uint32_t b1)
{
    asm volatile(
        "mma.sync.aligned.m16n8k16.row.col.f32.f16.f16.f32 "
        "{%0,%1,%2,%3},{%4,%5,%6,%7},{%8,%9},{%0,%1,%2,%3};"
        : "+f"(c[0]), "+f"(c[1]), "+f"(c[2]), "+f"(c[3])
        : "r"(a0), "r"(a1), "r"(a2), "r"(a3), "r"(b0), "r"(b1));
}
__device__ __forceinline__ void ldm_x4(uint32_t& r0, uint32_t& r1,
                                       uint32_t& r2, uint32_t& r3, uint32_t a)
{
    asm volatile("ldmatrix.sync.aligned.m8n8.x4.shared.b16 {%0,%1,%2,%3}, [%4];"
                 : "=r"(r0), "=r"(r1), "=r"(r2), "=r"(r3) : "r"(a));
}
__device__ __forceinline__ void ldm_x4_trans(uint32_t& r0, uint32_t& r1,
                                             uint32_t& r2, uint32_t& r3, uint32_t a)
{
    asm volatile("ldmatrix.sync.aligned.m8n8.x4.trans.shared.b16 {%0,%1,%2,%3}, [%4];"
                 : "=r"(r0), "=r"(r1), "=r"(r2), "=r"(r3) : "r"(a));
}
#define CP_ASYNC16(dst_u32, src_ptr) \
    asm volatile("cp.async.cg.shared.global [%0], [%1], 16;" \
                 :: "r"(dst_u32), "l"(src_ptr) : "memory")
#define CP_COMMIT() asm volatile("cp.async.commit_group;" ::: "memory")
#define CP_WAIT0()  asm volatile("cp.async.wait_group 0;" ::: "memory")

__device__ __forceinline__ void split2(float x, float y, uint32_t& h, uint32_t& l)
{
    __nv_bfloat162 hh = __floats2bfloat162_rn(x, y);
    float rx = x - __bfloat162float(__low2bfloat16(hh));
    float ry = y - __bfloat162float(__high2bfloat16(hh));
    __nv_bfloat162 ll = __floats2bfloat162_rn(rx, ry);
    h = *(uint32_t*)&hh;
    l = *(uint32_t*)&ll;
}

// ---------------------------------------------------------------------------
// Mask normalization
// ---------------------------------------------------------------------------
__global__ __launch_bounds__(1024) void mask_prep_kernel(const void* __restrict__ mraw)
{
    __shared__ int s_notint, s_notfloat;
    if (threadIdx.x == 0) { s_notint = 0; s_notfloat = 0; }
    __syncthreads();

    const unsigned int* u = (const unsigned int*)mraw;
    const unsigned char* b = (const unsigned char*)mraw;
    const int NM = NB * L_DIM;

    int notint = 0, notfloat = 0;
    for (int i = threadIdx.x; i < NM / 4; i += 1024) {
        unsigned int v = u[i];
        if (v > 1u) notint = 1;
        if (v != 0u && v != 0x3F800000u) notfloat = 1;
    }
    if (notint)   atomicOr(&s_notint, 1);
    if (notfloat) atomicOr(&s_notfloat, 1);
    __syncthreads();

    bool isWord = (s_notint == 0) || (s_notfloat == 0);
    for (int i = threadIdx.x; i < NM; i += 1024) {
        unsigned char m = isWord ? (unsigned char)(u[i] != 0u)
                                 : (unsigned char)(b[i] != 0);
        g_mask[i] = m;
    }
}

// ---------------------------------------------------------------------------
// LoRA first stage (merged): one block per token, warp w = rank r.
// mode 0: computes xa for q,k,v (A0,A1,A2) reading X once.
// mode 1: computes xa for o (A0) from g_ao.
// ---------------------------------------------------------------------------
__global__ __launch_bounds__(256) void lora_xa_kernel(
    const float* __restrict__ Xext,
    const float* __restrict__ A0, const float* __restrict__ A1,
    const float* __restrict__ A2, int mode)
{
    const float* X = mode ? g_ao : Xext;
    int t = blockIdx.x;
    int warp = threadIdx.x >> 5, lane = threadIdx.x & 31;
    const float* x = X + (size_t)t * E_DIM;

    if (mode == 0) {
        const float* a0 = A0 + (size_t)warp * E_DIM;
        const float* a1 = A1 + (size_t)warp * E_DIM;
        const float* a2 = A2 + (size_t)warp * E_DIM;
        float s0 = 0.f, s1 = 0.f, s2 = 0.f;
        for (int i = lane * 4; i < E_DIM; i += 128) {
            float4 xv = *(const float4*)(x + i);
            float4 av = *(const float4*)(a0 + i);
            s0 += xv.x*av.x + xv.y*av.y + xv.z*av.z + xv.w*av.w;
            av = *(const float4*)(a1 + i);
            s1 += xv.x*av.x + xv.y*av.y + xv.z*av.z + xv.w*av.w;
            av = *(const float4*)(a2 + i);
            s2 += xv.x*av.x + xv.y*av.y + xv.z*av.z + xv.w*av.w;
        }
        #pragma unroll
        for (int off = 16; off; off >>= 1) {
            s0 += __shfl_xor_sync(0xffffffffu, s0, off);
            s1 += __shfl_xor_sync(0xffffffffu, s1, off);
            s2 += __shfl_xor_sync(0xffffffffu, s2, off);
        }
        if (lane == 0) {
            g_xa[(size_t)t * R_DIM + warp] = s0;
            g_xa[(size_t)T_DIM * R_DIM + (size_t)t * R_DIM + warp] = s1;
            g_xa[(size_t)2 * T_DIM * R_DIM + (size_t)t * R_DIM + warp] = s2;
        }
    } else {
        const float* a = A0 + (size_t)warp * E_DIM;
        float s = 0.f;
        for (int i = lane * 4; i < E_DIM; i += 128) {
            float4 xv = *(const float4*)(x + i);
            float4 av = *(const float4*)(a + i);
            s += xv.x*av.x + xv.y*av.y + xv.z*av.z + xv.w*av.w;
        }
        #pragma unroll
        for (int off = 16; off; off >>= 1) s += __shfl_xor_sync(0xffffffffu, s, off);
        if (lane == 0)
            g_xa[(size_t)3 * T_DIM * R_DIM + (size_t)t * R_DIM + warp] = s;
    }
}

// ---------------------------------------------------------------------------
// Projection GEMM on mma.sync bf16 hi/lo split (r14 known-good version).
// ---------------------------------------------------------------------------
#define P_LDA 40

__global__ __launch_bounds__(256) void proj_mma_kernel(
    const float* __restrict__ Xext,
    const float* __restrict__ W0, const float* __restrict__ b0, const float* __restrict__ Bl0,
    const float* __restrict__ W1, const float* __restrict__ b1, const float* __restrict__ Bl1,
    const float* __restrict__ W2, const float* __restrict__ b2, const float* __restrict__ Bl2,
    float* __restrict__ Oext, int mode, float oscale0)
{
    int z = blockIdx.z;
    const float* X    = mode ? g_ao : Xext;
    const float* W    = (z == 0) ? W0  : (z == 1) ? W1  : W2;
    const float* bias = (z == 0) ? b0  : (z == 1) ? b1  : b2;
    const float* Bl   = (z == 0) ? Bl0 : (z == 1) ? Bl1 : Bl2;
    const float* xa   = g_xa + ((size_t)(mode ? 3 : z)) * T_DIM * R_DIM;
    float oscale      = (mode == 0 && z == 0) ? oscale0 : 1.0f;

    int kind;                        // 0 = bf16 hi/lo, 1 = fp16, 2 = fp32
    __nv_bfloat16 *Oh = nullptr, *Ol = nullptr;
    __half* Of = nullptr;
    float* O32 = nullptr;
    if (mode) { kind = 2; O32 = Oext; }
    else if (z == 0) { kind = 0; Oh = g_qh; Ol = g_ql; }
    else if (z == 1) { kind = 0; Oh = g_kh; Ol = g_kl; }
    else { kind = 1; Of = g_vf; }

    const int m0 = blockIdx.y * 128;
    const int n0 = blockIdx.x * 128;

    __shared__ __nv_bfloat16 Ah[128 * P_LDA], Al[128 * P_LDA];
    __shared__ __nv_bfloat16 Bh[128 * P_LDA], Blo[128 * P_LDA];
    __shared__ float lora_sm[128 * 8];
    __shared__ float bias_sm[128];

    int tid = threadIdx.x;
    int wid = tid >> 5, lane = tid & 31;
    int warp_m = wid & 1;
    int warp_n = wid >> 1;

    for (int i = tid; i < 128 * 8; i += 256)
        lora_sm[i] = Bl[(size_t)(n0 + (i >> 3)) * R_DIM + (i & 7)];
    for (int i = tid; i < 128; i += 256)
        bias_sm[i] = bias[n0 + i];

    float acc[4][4][4];
    #pragma unroll
    for (int mt = 0; mt < 4; mt++)
        #pragma unroll
        for (int nt = 0; nt < 4; nt++)
            #pragma unroll
            for (int r = 0; r < 4; r++) acc[mt][nt][r] = 0.f;

    for (int kc = 0; kc < E_DIM / 32; kc++) {
        int k0 = kc * 32;
        #pragma unroll
        for (int i = 0; i < 4; i++) {
            int idx = tid + i * 256;
            int row = idx >> 3;
            int fq = (idx & 7) * 4;
            float4 va = *(const float4*)&X[(size_t)(m0 + row) * E_DIM + k0 + fq];
            uint32_t h0, l0, h1, l1;
            split2(va.x, va.y, h0, l0);
            split2(va.z, va.w, h1, l1);
            *(uint2*)&Ah[row * P_LDA + fq] = make_uint2(h0, h1);
            *(uint2*)&Al[row * P_LDA + fq] = make_uint2(l0, l1);
            float4 vb = *(const float4*)&W[(size_t)(n0 + row) * E_DIM + k0 + fq];
            split2(vb.x, vb.y, h0, l0);
            split2(vb.z, vb.w, h1, l1);
            *(uint2*)&Bh[row * P_LDA + fq] = make_uint2(h0, h1);
            *(uint2*)&Blo[row * P_LDA + fq] = make_uint2(l0, l1);
        }
        __syncthreads();

        #pragma unroll
        for (int ks = 0; ks < 32; ks += 16) {
            uint32_t ahf[4][4], alf[4][4];
            #pragma unroll
            for (int mt = 0; mt < 4; mt++) {
                int r = warp_m * 64 + mt * 16 + (lane >> 2);
                int kk = ks + (lane & 3) * 2;
                ahf[mt][0] = *(uint32_t*)&Ah[r * P_LDA + kk];
                ahf[mt][1] = *(uint32_t*)&Ah[(r + 8) * P_LDA + kk];
                ahf[mt][2] = *(uint32_t*)&Ah[r * P_LDA + kk + 8];
                ahf[mt][3] = *(uint32_t*)&Ah[(r + 8) * P_LDA + kk + 8];
                alf[mt][0] = *(uint32_t*)&Al[r * P_LDA + kk];
                alf[mt][1] = *(uint32_t*)&Al[(r + 8) * P_LDA + kk];
                alf[mt][2] = *(uint32_t*)&Al[r * P_LDA + kk + 8];
                alf[mt][3] = *(uint32_t*)&Al[(r + 8) * P_LDA + kk + 8];
            }
            uint32_t bhf[4][2], blf[4][2];
            #pragma unroll
            for (int nt = 0; nt < 4; nt++) {
                int c = warp_n * 32 + nt * 8 + (lane >> 2);
                int kk = ks + (lane & 3) * 2;
                bhf[nt][0] = *(uint32_t*)&Bh[c * P_LDA + kk];
                bhf[nt][1] = *(uint32_t*)&Bh[c * P_LDA + kk + 8];
                blf[nt][0] = *(uint32_t*)&Blo[c * P_LDA + kk];
                blf[nt][1] = *(uint32_t*)&Blo[c * P_LDA + kk + 8];
            }
            #pragma unroll
            for (int mt = 0; mt < 4; mt++)
                #pragma unroll
                for (int nt = 0; nt < 4; nt++) {
                    mma_bf16(acc[mt][nt], ahf[mt][0], ahf[mt][1], ahf[mt][2], ahf[mt][3],
                             bhf[nt][0], bhf[nt][1]);
                    mma_bf16(acc[mt][nt], ahf[mt][0], ahf[mt][1], ahf[mt][2], ahf[mt][3],
                             blf[nt][0], blf[nt][1]);
                    mma_bf16(acc[mt][nt], alf[mt][0], alf[mt][1], alf[mt][2], alf[mt][3],
                             bhf[nt][0], bhf[nt][1]);
                }
        }
        __syncthreads();
    }

    #pragma unroll
    for (int mt = 0; mt < 4; mt++) {
        int r0 = m0 + warp_m * 64 + mt * 16 + (lane >> 2);
        int r1 = r0 + 8;
        float xr0[8], xr1[8];
        *(float4*)(xr0)     = *(const float4*)&xa[(size_t)r0 * R_DIM];
        *(float4*)(xr0 + 4) = *(const float4*)&xa[(size_t)r0 * R_DIM + 4];
        *(float4*)(xr1)     = *(const float4*)&xa[(size_t)r1 * R_DIM];
        *(float4*)(xr1 + 4) = *(const float4*)&xa[(size_t)r1 * R_DIM + 4];
        #pragma unroll
        for (int nt = 0; nt < 4; nt++) {
            int col = warp_n * 32 + nt * 8 + (lane & 3) * 2;
            const float* bl0 = &lora_sm[col * 8];
            const float* bl1 = &lora_sm[(col + 1) * 8];
            float lr00 = 0.f, lr01 = 0.f, lr10 = 0.f, lr11 = 0.f;
            #pragma unroll
            for (int r = 0; r < 8; r++) {
                lr00 += xr0[r] * bl0[r];
                lr01 += xr0[r] * bl1[r];
                lr10 += xr1[r] * bl0[r];
                lr11 += xr1[r] * bl1[r];
            }
            float2 v0, v1;
            v0.x = (acc[mt][nt][0] + bias_sm[col]     + LORA_SCALE * lr00) * oscale;
            v0.y = (acc[mt][nt][1] + bias_sm[col + 1] + LORA_SCALE * lr01) * oscale;
            v1.x = (acc[mt][nt][2] + bias_sm[col]     + LORA_SCALE * lr10) * oscale;
            v1.y = (acc[mt][nt][3] + bias_sm[col + 1] + LORA_SCALE * lr11) * oscale;
            size_t o0 = (size_t)r0 * E_DIM + n0 + col;
            size_t o1 = (size_t)r1 * E_DIM + n0 + col;
            if (kind == 0) {
                uint32_t h, l;
                split2(v0.x, v0.y, h, l);
                *(uint32_t*)&Oh[o0] = h; *(uint32_t*)&Ol[o0] = l;
                split2(v1.x, v1.y, h, l);
                *(uint32_t*)&Oh[o1] = h; *(uint32_t*)&Ol[o1] = l;
            } else if (kind == 1) {
                *(__half2*)&Of[o0] = __floats2half2_rn(v0.x, v0.y);
                *(__half2*)&Of[o1] = __floats2half2_rn(v1.x, v1.y);
            } else {
                *(float2*)&O32[o0] = v0;
                *(float2*)&O32[o1] = v1;
            }
        }
    }
}

// ---------------------------------------------------------------------------
// Fused attention (r14 known-good): cp.async double-buffered K/V + ldmatrix +
// smem-staged coalesced w' stores.
// ---------------------------------------------------------------------------
#define QLD 72
#define QARR (128*QLD*2)          // 18432 B
#define KARR (64*QLD*2)           // 9216 B
#define OFF_QH 0
#define OFF_QL QARR
#define OFF_KV (2*QARR)           // per buf {KH, KL, V} = 3*KARR
#define KVSTRIDE (3*KARR)         // 27648
#define OFF_MS (OFF_KV + 2*KVSTRIDE)   // 92160
#define WLD 72
#define OFF_WST (OFF_MS + 2048)        // 94208
#define ATT_SMEM (OFF_WST + 128*WLD*2) // 112640

__global__ __launch_bounds__(256, 2) void attn_fused_kernel()
{
    extern __shared__ char smem[];
    unsigned char* msk_s = (unsigned char*)(smem + OFF_MS);
    __half* wst = (__half*)(smem + OFF_WST);
    const uint32_t sbase = (uint32_t)__cvta_generic_to_shared(smem);

    int z = blockIdx.y;
    int n = z >> 4, h = z & 15;
    const size_t hb = (size_t)n * E_DIM + h * HD_DIM;
    const size_t zb = (size_t)z * L_DIM * L_DIM;
    const int lda = NB * E_DIM;
    const int m0 = blockIdx.x * 128;

    int tid = threadIdx.x;
    int wid = tid >> 5, lane = tid & 31;
    const int rg0 = m0 + wid * 16 + (lane >> 2);

    #pragma unroll
    for (int i = 0; i < 4; i++) {
        int idx = tid + i * 256;
        int row = idx >> 3;
        int hq = (idx & 7) * 8;
        size_t go = hb + (size_t)(m0 + row) * lda + hq;
        uint32_t d = sbase + OFF_QH + (row * QLD + hq) * 2;
        CP_ASYNC16(d, &g_qh[go]);
        CP_ASYNC16(d + QARR, &g_ql[go]);
    }
    for (int i = tid; i < L_DIM; i += 256)
        msk_s[i] = g_mask[n * L_DIM + i];

    #pragma unroll
    for (int i = 0; i < 2; i++) {
        int idx = tid + i * 256;
        int row = idx >> 3;
        int hq = (idx & 7) * 8;
        size_t go = hb + (size_t)(row) * lda + hq;
        uint32_t d = sbase + OFF_KV + (row * QLD + hq) * 2;
        CP_ASYNC16(d, &g_kh[go]);
        CP_ASYNC16(d + KARR, &g_kl[go]);
        CP_ASYNC16(d + 2 * KARR, &g_vf[go]);
    }
    CP_COMMIT();

    const int frow = ((lane >> 3) & 1) * 8 + (lane & 7);
    const int fcol = (lane >> 4) * 8;
    const uint32_t uQh = sbase + OFF_QH + ((wid * 16 + frow) * QLD + fcol) * 2;
    const uint32_t uQl = uQh + QARR;
    const int vrow = ((lane >> 4) << 3) + (lane & 7);
    const int vcol = ((lane >> 3) & 1) << 3;

    const int srow = wid * 16 + (lane >> 2);
    const int scol = (lane & 3) * 2;

    float m0r = -FLT_MAX, m1r = -FLT_MAX, s0 = 0.f, s1 = 0.f;
    float acc[8][4];
    #pragma unroll
    for (int dt = 0; dt < 8; dt++)
        #pragma unroll
        for (int r = 0; r < 4; r++) acc[dt][r] = 0.f;

    int buf = 0;
    for (int kt = 0; kt < NTILES; kt++) {
        CP_WAIT0();
        __syncthreads();

        if (kt + 1 < NTILES) {
            int kb = (kt + 1) * KT;
            uint32_t dst = sbase + OFF_KV + (buf ^ 1) * KVSTRIDE;
            #pragma unroll
            for (int i = 0; i < 2; i++) {
                int idx = tid + i * 256;
                int row = idx >> 3;
                int hq = (idx & 7) * 8;
                size_t go = hb + (size_t)(kb + row) * lda + hq;
                uint32_t d = dst + (row * QLD + hq) * 2;
                CP_ASYNC16(d, &g_kh[go]);
                CP_ASYNC16(d + KARR, &g_kl[go]);
                CP_ASYNC16(d + 2 * KARR, &g_vf[go]);
            }
            CP_COMMIT();
        }

        const uint32_t uKh = sbase + OFF_KV + buf * KVSTRIDE + (frow * QLD + fcol) * 2;
        const uint32_t uKl = uKh + KARR;
        const uint32_t uV  = sbase + OFF_KV + buf * KVSTRIDE + 2 * KARR
                           + (vrow * QLD + vcol) * 2;
        int kbase = kt * KT;

        float f[8][4];
        #pragma unroll
        for (int nt = 0; nt < 8; nt++)
            #pragma unroll
            for (int r = 0; r < 4; r++) f[nt][r] = 0.f;

        #pragma unroll
        for (int ks = 0; ks < 4; ks++) {
            uint32_t qh0, qh1, qh2, qh3, ql0, ql1, ql2, ql3;
            ldm_x4(qh0, qh1, qh2, qh3, uQh + ks * 32);
            ldm_x4(ql0, ql1, ql2, ql3, uQl + ks * 32);
            #pragma unroll
            for (int ntp = 0; ntp < 4; ntp++) {
                uint32_t bhA0, bhB0, bhA1, bhB1, blA0, blB0, blA1, blB1;
                ldm_x4(bhA0, bhB0, bhA1, bhB1, uKh + (ntp * 16 * QLD) * 2 + ks * 32);
                ldm_x4(blA0, blB0, blA1, blB1, uKl + (ntp * 16 * QLD) * 2 + ks * 32);
                mma_bf16(f[2*ntp],   qh0, qh1, qh2, qh3, bhA0, bhA1);
                mma_bf16(f[2*ntp],   qh0, qh1, qh2, qh3, blA0, blA1);
                mma_bf16(f[2*ntp],   ql0, ql1, ql2, ql3, bhA0, bhA1);
                mma_bf16(f[2*ntp+1], qh0, qh1, qh2, qh3, bhB0, bhB1);
                mma_bf16(f[2*ntp+1], qh0, qh1, qh2, qh3, blB0, blB1);
                mma_bf16(f[2*ntp+1], ql0, ql1, ql2, ql3, bhB0, bhB1);
            }
        }

        int cb = kbase + (lane & 3) * 2;
        float tm0 = -FLT_MAX, tm1 = -FLT_MAX;
        unsigned mka = 0, mkb = 0;
        #pragma unroll
        for (int nt = 0; nt < 8; nt++) {
            bool ma = msk_s[cb + nt * 8] != 0;
            bool mb = msk_s[cb + nt * 8 + 1] != 0;
            if (ma) mka |= (1u << nt);
            if (mb) mkb |= (1u << nt);
            tm0 = fmaxf(tm0, ma ? -FLT_MAX : f[nt][0]);
            tm0 = fmaxf(tm0, mb ? -FLT_MAX : f[nt][1]);
            tm1 = fmaxf(tm1, ma ? -FLT_MAX : f[nt][2]);
            tm1 = fmaxf(tm1, mb ? -FLT_MAX : f[nt][3]);
        }
        tm0 = fmaxf(tm0, __shfl_xor_sync(0xffffffffu, tm0, 1));
        tm0 = fmaxf(tm0, __shfl_xor_sync(0xffffffffu, tm0, 2));
        tm1 = fmaxf(tm1, __shfl_xor_sync(0xffffffffu, tm1, 1));
        tm1 = fmaxf(tm1, __shfl_xor_sync(0xffffffffu, tm1, 2));

        float mn0 = fmaxf(m0r, tm0);
        float mn1 = fmaxf(m1r, tm1);
        float sc0 = __expf(m0r - mn0);
        float sc1 = __expf(m1r - mn1);
        s0 *= sc0; s1 *= sc1;
        #pragma unroll
        for (int dt = 0; dt < 8; dt++) {
            acc[dt][0] *= sc0; acc[dt][1] *= sc0;
            acc[dt][2] *= sc1; acc[dt][3] *= sc1;
        }
        m0r = mn0; m1r = mn1;

        uint32_t wA[8], wB[8];
        #pragma unroll
        for (int nt = 0; nt < 8; nt++) {
            bool ma = (mka >> nt) & 1, mb = (mkb >> nt) & 1;
            float e0 = ma ? 0.f : __expf(f[nt][0] - mn0);
            float e1 = mb ? 0.f : __expf(f[nt][1] - mn0);
            float e2 = ma ? 0.f : __expf(f[nt][2] - mn1);
            float e3 = mb ? 0.f : __expf(f[nt][3] - mn1);
            s0 += e0 + e1;
            s1 += e2 + e3;
            __half2 w01 = __floats2half2_rn(e0, e1);
            __half2 w23 = __floats2half2_rn(e2, e3);
            wA[nt] = *(uint32_t*)&w01;
            wB[nt] = *(uint32_t*)&w23;
            int col = scol + nt * 8;
            *(uint32_t*)&wst[srow * WLD + col] = wA[nt];
            *(uint32_t*)&wst[(srow + 8) * WLD + col] = wB[nt];
        }
        if ((lane & 3) == 0) {
            g_mtile[((size_t)z * NTILES + kt) * L_DIM + rg0] = mn0;
            g_mtile[((size_t)z * NTILES + kt) * L_DIM + rg0 + 8] = mn1;
        }

        #pragma unroll
        for (int kk = 0; kk < 4; kk++) {
            uint32_t vbase = uV + (kk * 16 * QLD) * 2;
            #pragma unroll
            for (int dtp = 0; dtp < 4; dtp++) {
                uint32_t vA0, vB0, vA1, vB1;
                ldm_x4_trans(vA0, vB0, vA1, vB1, vbase + (dtp * 16) * 2);
                mma_f16(acc[2*dtp],   wA[2*kk], wB[2*kk], wA[2*kk+1], wB[2*kk+1], vA0, vA1);
                mma_f16(acc[2*dtp+1], wA[2*kk], wB[2*kk], wA[2*kk+1], wB[2*kk+1], vB0, vB1);
            }
        }

        __syncthreads();
        #pragma unroll
        for (int i = 0; i < 4; i++) {
            int idx = tid + i * 256;
            int row = idx >> 3;
            int cq = (idx & 7) * 8;
            uint4 v = *(const uint4*)&wst[row * WLD + cq];
            *(uint4*)&g_w[zb + (size_t)(m0 + row) * L_DIM + kbase + cq] = v;
        }
        buf ^= 1;
    }

    s0 += __shfl_xor_sync(0xffffffffu, s0, 1);
    s0 += __shfl_xor_sync(0xffffffffu, s0, 2);
    s1 += __shfl_xor_sync(0xffffffffu, s1, 1);
    s1 += __shfl_xor_sync(0xffffffffu, s1, 2);

    float inv0 = (s0 > 0.f) ? 1.f / s0 : 0.f;
    float inv1 = (s1 > 0.f) ? 1.f / s1 : 0.f;
    if ((lane & 3) == 0) {
        g_mfin[(size_t)z * L_DIM + rg0] = m0r;
        g_mfin[(size_t)z * L_DIM + rg0 + 8] = m1r;
        g_sfin[(size_t)z * L_DIM + rg0] = s0;
        g_sfin[(size_t)z * L_DIM + rg0 + 8] = s1;
    }
    #pragma unroll
    for (int dt = 0; dt < 8; dt++) {
        int d = dt * 8 + (lane & 3) * 2;
        *(float2*)&g_ao[((size_t)rg0 * NB + n) * E_DIM + h * HD_DIM + d] =
            make_float2(acc[dt][0] * inv0, acc[dt][1] * inv0);
        *(float2*)&g_ao[((size_t)(rg0 + 8) * NB + n) * E_DIM + h * HD_DIM + d] =
            make_float2(acc[dt][2] * inv1, acc[dt][3] * inv1);
    }
}

// ---------------------------------------------------------------------------
// Head-mean of normalized weights
// ---------------------------------------------------------------------------
__global__ __launch_bounds__(256) void mean_kernel(float* __restrict__ out2)
{
    int l = blockIdx.x, n = blockIdx.y;
    __shared__ float fac[NTILES];
    int tid = threadIdx.x;
    int c0 = tid * 8;

    float wacc[8];
    #pragma unroll
    for (int j = 0; j < 8; j++) wacc[j] = 0.f;

    for (int h = 0; h < H_DIM; h++) {
        int z = n * H_DIM + h;
        if (tid < NTILES) {
            float mf = g_mfin[(size_t)z * L_DIM + l];
            float s  = g_sfin[(size_t)z * L_DIM + l];
            float inv = (s > 0.f) ? 1.f / s : 0.f;
            float mt = g_mtile[((size_t)z * NTILES + tid) * L_DIM + l];
            fac[tid] = __expf(mt - mf) * inv;
        }
        __syncthreads();
        float fc = fac[c0 >> 6];
        uint4 raw = *(const uint4*)&g_w[(size_t)z * L_DIM * L_DIM + (size_t)l * L_DIM + c0];
        const __half2* hp = (const __half2*)&raw;
        #pragma unroll
        for (int q = 0; q < 4; q++) {
            float2 v = __half22float2(hp[q]);
            wacc[q * 2]     += v.x * fc;
            wacc[q * 2 + 1] += v.y * fc;
        }
        __syncthreads();
    }

    const float invH = 1.0f / H_DIM;
    float4 o0 = make_float4(wacc[0]*invH, wacc[1]*invH, wacc[2]*invH, wacc[3]*invH);
    float4 o1 = make_float4(wacc[4]*invH, wacc[5]*invH, wacc[6]*invH, wacc[7]*invH);
    *(float4*)&out2[((size_t)l * NB + n) * L_DIM + c0]     = o0;
    *(float4*)&out2[((size_t)l * NB + n) * L_DIM + c0 + 4] = o1;
}

// ---------------------------------------------------------------------------
extern "C" void kernel_launch(void* const* d_in, const int* in_sizes, int n_in,
                              void* d_out, int out_size)
{
    (void)in_sizes; (void)n_in; (void)out_size;
    const float* query = (const float*)d_in[0];
    const void* mask_raw = d_in[1];
    const float* Wq = (const float*)d_in[2];
    const float* bq = (const float*)d_in[3];
    const float* Aq = (const float*)d_in[4];
    const float* Bq = (const float*)d_in[5];
    const float* Wk = (const float*)d_in[6];
    const float* bk = (const float*)d_in[7];
    const float* Ak = (const float*)d_in[8];
    const float* Bk = (const float*)d_in[9];
    const float* Wv = (const float*)d_in[10];
    const float* bv = (const float*)d_in[11];
    const float* Av = (const float*)d_in[12];
    const float* Bv = (const float*)d_in[13];
    const float* Wo = (const float*)d_in[14];
    const float* bo = (const float*)d_in[15];
    const float* Ao = (const float*)d_in[16];
    const float* Bo = (const float*)d_in[17];

    float* out  = (float*)d_out;
    float* out2 = out + (size_t)T_DIM * E_DIM;

    cudaFuncSetAttribute(attn_fused_kernel,
                         cudaFuncAttributeMaxDynamicSharedMemorySize, ATT_SMEM);

    // 0. Normalize mask encoding
    mask_prep_kernel<<<1, 1024>>>(mask_raw);
    // 1. LoRA x@A^T for q,k,v (merged: X read once)
    lora_xa_kernel<<<T_DIM, 256>>>(query, Aq, Ak, Av, 0);
    // 2. Q/K/V projections (q scaled; outputs pre-split bf16 / fp16)
    proj_mma_kernel<<<dim3(8, 32, 3), 256>>>(query, Wq, bq, Bq, Wk, bk, Bk,
                                             Wv, bv, Bv, nullptr, 0, ATTN_SCALE);
    // 3. Fused QK + online softmax + AV (cp.async + ldmatrix)
    attn_fused_kernel<<<dim3(16, 32), 256, ATT_SMEM>>>();
    // 4. Head-mean weights output
    mean_kernel<<<dim3(L_DIM, NB), 256>>>(out2);
    // 5. LoRA x@A^T for output projection
    lora_xa_kernel<<<T_DIM, 256>>>(nullptr, Ao, Ao, Ao, 1);
    // 6. Output projection -> d_out
    proj_mma_kernel<<<dim3(8, 32, 1), 256>>>(nullptr, Wo, bo, Bo, Wo, bo, Bo,
                                             Wo, bo, Bo, out, 1, 1.0f);
}